// round 1
// baseline (speedup 1.0000x reference)
#include <cuda_runtime.h>

#define PP        4096
#define HH        256
#define NSTEPS    100
#define DTC       0.1f
#define SQRT_DTC  0.31622776601683794f
#define ROWS      16      // particles per block
#define RSTRIDE   20      // padded row stride (floats) for act[k][r]; 80B keeps 16B align
#define NTHREADS  256

// Carried recurrent state (allocation-free scratch).
__device__ float g_state[PP * 2];

__device__ __forceinline__ float softplusf(float x) {
    // matches jax.nn.softplus == logaddexp(x, 0) == max(x,0) + log1p(exp(-|x|))
    return fmaxf(x, 0.0f) + log1pf(expf(-fabsf(x)));
}

__device__ __forceinline__ unsigned long long pack2(float lo, float hi) {
    unsigned long long r;
    asm("mov.b64 %0, {%1, %2};" : "=l"(r) : "f"(lo), "f"(hi));
    return r;
}
__device__ __forceinline__ void unpack2(unsigned long long v, float& lo, float& hi) {
    asm("mov.b64 {%0, %1}, %2;" : "=f"(lo), "=f"(hi) : "l"(v));
}
// packed fp32 pair FMA: d = a*b + d  (2 FMAs per instruction on sm_103a)
__device__ __forceinline__ void fma2(unsigned long long& d, unsigned long long a,
                                     unsigned long long b) {
    asm("fma.rn.f32x2 %0, %1, %2, %0;" : "+l"(d) : "l"(a), "l"(b));
}

// One 256->256 layer with relu: act[k][r] (shared, k-major) -> nxt[n][r].
// Thread tid owns output column n = tid for all ROWS rows.
__device__ __forceinline__ void mlp_layer(const float* act, float* nxt,
                                          const float* __restrict__ W,
                                          const float* __restrict__ b, int tid) {
    float bb = __ldg(b + tid);
    unsigned long long bp = pack2(bb, bb);
    unsigned long long acc[ROWS / 2];
#pragma unroll
    for (int i = 0; i < ROWS / 2; i++) acc[i] = bp;

    const float* wp = W + tid;
#pragma unroll 8
    for (int k = 0; k < HH; k++) {
        float w = __ldg(wp + k * HH);           // coalesced, L2-resident
        unsigned long long w2 = pack2(w, w);
        const ulonglong2* arow = reinterpret_cast<const ulonglong2*>(act + k * RSTRIDE);
#pragma unroll
        for (int q = 0; q < ROWS / 4; q++) {
            ulonglong2 a = arow[q];             // broadcast LDS.128 (all lanes same addr)
            fma2(acc[2 * q + 0], a.x, w2);
            fma2(acc[2 * q + 1], a.y, w2);
        }
    }
#pragma unroll
    for (int i = 0; i < ROWS / 2; i++) {
        float lo, hi;
        unpack2(acc[i], lo, hi);
        nxt[tid * RSTRIDE + 2 * i + 0] = fmaxf(lo, 0.0f);
        nxt[tid * RSTRIDE + 2 * i + 1] = fmaxf(hi, 0.0f);
    }
}

__global__ void __launch_bounds__(NTHREADS, 2) lv_step_kernel(
    const float* __restrict__ W0, const float* __restrict__ b0,
    const float* __restrict__ W1, const float* __restrict__ b1,
    const float* __restrict__ W2, const float* __restrict__ b2,
    const float* __restrict__ W3, const float* __restrict__ b3,
    const float* __restrict__ obs_init, const float* __restrict__ feature_init,
    const float* __restrict__ tn_store, const float* __restrict__ x1_store,
    const float* __restrict__ x2_store, const float* __restrict__ path_seed,
    float* __restrict__ out, int s) {
    __shared__ __align__(16) float actA[HH * RSTRIDE];
    __shared__ __align__(16) float actB[HH * RSTRIDE];
    __shared__ float inp_sh[ROWS][8];
    __shared__ float w3_sh[HH * 5];
    __shared__ float b3_sh[5];

    int tid = threadIdx.x;
    int row0 = blockIdx.x * ROWS;

    // stage W3/b3 into shared
    for (int i = tid; i < HH * 5; i += NTHREADS) w3_sh[i] = W3[i];
    if (tid < 5) b3_sh[tid] = b3[tid];

    // stage state (2 dims per particle)
    if (tid < ROWS * 2) {
        int r = tid >> 1, d = tid & 1;
        int p = row0 + r;
        inp_sh[r][d] = (s == 0) ? obs_init[p * 2 + d] : g_state[p * 2 + d];
    }
    // stage features
    if (s == 0) {
        if (tid >= 32 && tid < 32 + ROWS * 6) {
            int q = tid - 32;
            int r = q / 6, k = q % 6;
            inp_sh[r][2 + k] = feature_init[(row0 + r) * 6 + k];
        }
    } else {
        if (tid == 32) {
            // replicate the reference's sequential fp32 time accumulation exactly
            float t = feature_init[0];
            for (int j = 0; j < s; j++) t += DTC;
            int i = s - 1;
            float f1 = tn_store[i], f2 = x1_store[i], f3 = x2_store[i];
#pragma unroll
            for (int r = 0; r < ROWS; r++) {
                inp_sh[r][2] = t;  inp_sh[r][3] = f1; inp_sh[r][4] = f2;
                inp_sh[r][5] = f3; inp_sh[r][6] = f2; inp_sh[r][7] = f3;
            }
        }
    }
    __syncthreads();

    // layer 0: (rows x 8) @ (8 x 256) + relu -> actA[k][r]
    {
        float w0c[8];
#pragma unroll
        for (int k = 0; k < 8; k++) w0c[k] = W0[k * HH + tid];
        float bb = b0[tid];
#pragma unroll
        for (int r = 0; r < ROWS; r++) {
            float a = bb;
#pragma unroll
            for (int k = 0; k < 8; k++) a = fmaf(inp_sh[r][k], w0c[k], a);
            actA[tid * RSTRIDE + r] = fmaxf(a, 0.0f);
        }
    }
    __syncthreads();

    mlp_layer(actA, actB, W1, b1, tid);
    __syncthreads();
    mlp_layer(actB, actA, W2, b2, tid);
    __syncthreads();

    // layer 3: (rows x 256) @ (256 x 5), split-K over 16 lanes per row
    int r = tid >> 4;
    int l16 = tid & 15;
    float acc5[5] = {0.f, 0.f, 0.f, 0.f, 0.f};
#pragma unroll
    for (int kk = 0; kk < 16; kk++) {
        int k = l16 + (kk << 4);                 // strided k -> ~2-way LDS conflicts only
        float a = actA[k * RSTRIDE + r];
#pragma unroll
        for (int m = 0; m < 5; m++) acc5[m] = fmaf(a, w3_sh[k * 5 + m], acc5[m]);
    }
#pragma unroll
    for (int off = 8; off >= 1; off >>= 1) {
#pragma unroll
        for (int m = 0; m < 5; m++)
            acc5[m] += __shfl_down_sync(0xffffffffu, acc5[m], off, 16);
    }

    if (l16 == 0) {
        int p = row0 + r;
        float mu0 = acc5[0] + b3_sh[0];
        float mu1 = acc5[1] + b3_sh[1];
        float s11 = softplusf(acc5[2] + b3_sh[2]);
        float s21 = acc5[3] + b3_sh[3];
        float s22 = softplusf(acc5[4] + b3_sh[4]);
        float st0 = inp_sh[r][0], st1 = inp_sh[r][1];
        float e0 = path_seed[s * PP * 2 + p * 2 + 0];
        float e1 = path_seed[s * PP * 2 + p * 2 + 1];
        float n0 = softplusf(st0 + DTC * mu0 + SQRT_DTC * (s11 * e0));
        float n1 = softplusf(st1 + DTC * mu1 + SQRT_DTC * (s21 * e0 + s22 * e1));
        g_state[p * 2 + 0] = n0;
        g_state[p * 2 + 1] = n1;

        // path: out[p*202 + d*101 + t]; step s writes t = s+1
        out[p * 202 + (s + 1)]       = n0;
        out[p * 202 + 101 + (s + 1)] = n1;
        if (s == 0) {  // t = 0 comes from obs_init
            out[p * 202 + 0]   = st0;
            out[p * 202 + 101] = st1;
        }
        // mu_store: base P*202, [(p*100 + s)*2 + d]
        int mb = PP * 202 + (p * 100 + s) * 2;
        out[mb + 0] = mu0;
        out[mb + 1] = mu1;
        // sigma_store: base P*202 + P*200, [(p*100 + s)*4 + i*2 + j]
        int sb = PP * 202 + PP * 200 + (p * 100 + s) * 4;
        out[sb + 0] = s11;
        out[sb + 1] = 0.0f;   // chol[0][1]
        out[sb + 2] = s21;
        out[sb + 3] = s22;
    }
}

extern "C" void kernel_launch(void* const* d_in, const int* in_sizes, int n_in,
                              void* d_out, int out_size) {
    const float* W0 = (const float*)d_in[0];
    const float* b0 = (const float*)d_in[1];
    const float* W1 = (const float*)d_in[2];
    const float* b1 = (const float*)d_in[3];
    const float* W2 = (const float*)d_in[4];
    const float* b2 = (const float*)d_in[5];
    const float* b2W3 = nullptr; (void)b2W3;
    const float* W3 = (const float*)d_in[6];
    const float* b3 = (const float*)d_in[7];
    const float* obs_init = (const float*)d_in[8];
    const float* feature_init = (const float*)d_in[9];
    const float* tn_store = (const float*)d_in[10];
    const float* x1_store = (const float*)d_in[11];
    const float* x2_store = (const float*)d_in[12];
    const float* path_seed = (const float*)d_in[13];
    float* out = (float*)d_out;

    dim3 grid(PP / ROWS);   // 256 blocks
    dim3 block(NTHREADS);
    for (int s = 0; s < NSTEPS; s++) {
        lv_step_kernel<<<grid, block>>>(W0, b0, W1, b1, W2, b2, W3, b3,
                                        obs_init, feature_init, tn_store,
                                        x1_store, x2_store, path_seed, out, s);
    }
}

// round 2
// speedup vs baseline: 1.2220x; 1.2220x over previous
#include <cuda_runtime.h>

#define PP        4096
#define HH        256
#define NSTEPS    100
#define DTC       0.1f
#define SQRT_DTC  0.31622776601683794f
#define ROWS      8       // particles per block
#define NTHREADS  128
#define NBLOCKS   (PP / ROWS)   // 512

// Carried recurrent state (allocation-free scratch).
__device__ float g_state[PP * 2];

__device__ __forceinline__ float softplusf(float x) {
    // matches jax.nn.softplus == max(x,0) + log1p(exp(-|x|))
    return fmaxf(x, 0.0f) + log1pf(expf(-fabsf(x)));
}

__device__ __forceinline__ unsigned long long pack2(float lo, float hi) {
    unsigned long long r;
    asm("mov.b64 %0, {%1, %2};" : "=l"(r) : "f"(lo), "f"(hi));
    return r;
}
__device__ __forceinline__ void unpack2(unsigned long long v, float& lo, float& hi) {
    asm("mov.b64 {%0, %1}, %2;" : "=f"(lo), "=f"(hi) : "l"(v));
}
// packed fp32 pair FMA: d = a*b + d  (2 FMAs per instruction on sm_103a)
__device__ __forceinline__ void fma2(unsigned long long& d, unsigned long long a,
                                     unsigned long long b) {
    asm("fma.rn.f32x2 %0, %1, %2, %0;" : "+l"(d) : "l"(a), "l"(b));
}

// One 256->256 layer with relu: act[k][r] (k-major, 8 rows) -> nxt[n][r].
// Thread tid owns output columns n0=2*tid and n0+1 for all 8 rows.
// Per k: 1 LDG.64 (two weights) + 2 broadcast LDS.128 + 8 FFMA2.
__device__ __forceinline__ void mlp_layer(const float* act, float* nxt,
                                          const float* __restrict__ W,
                                          const float* __restrict__ b, int tid) {
    const int n0 = 2 * tid;
    float bv0 = __ldg(b + n0);
    float bv1 = __ldg(b + n0 + 1);
    unsigned long long accA[4], accB[4];
#pragma unroll
    for (int i = 0; i < 4; i++) { accA[i] = pack2(bv0, bv0); accB[i] = pack2(bv1, bv1); }

    const float2* wp = reinterpret_cast<const float2*>(W + n0);
#pragma unroll 8
    for (int k = 0; k < HH; k++) {
        float2 w = __ldg(wp + k * (HH / 2));          // LDG.64, coalesced, L2-resident
        unsigned long long w0 = pack2(w.x, w.x);
        unsigned long long w1 = pack2(w.y, w.y);
        const ulonglong2* arow = reinterpret_cast<const ulonglong2*>(act + k * ROWS);
        ulonglong2 a01 = arow[0];                      // broadcast LDS.128 (rows 0..3)
        ulonglong2 a23 = arow[1];                      // broadcast LDS.128 (rows 4..7)
        fma2(accA[0], a01.x, w0);
        fma2(accA[1], a01.y, w0);
        fma2(accA[2], a23.x, w0);
        fma2(accA[3], a23.y, w0);
        fma2(accB[0], a01.x, w1);
        fma2(accB[1], a01.y, w1);
        fma2(accB[2], a23.x, w1);
        fma2(accB[3], a23.y, w1);
    }
#pragma unroll
    for (int i = 0; i < 4; i++) {
        float lo, hi;
        unpack2(accA[i], lo, hi);
        nxt[n0 * ROWS + 2 * i + 0] = fmaxf(lo, 0.0f);
        nxt[n0 * ROWS + 2 * i + 1] = fmaxf(hi, 0.0f);
        unpack2(accB[i], lo, hi);
        nxt[(n0 + 1) * ROWS + 2 * i + 0] = fmaxf(lo, 0.0f);
        nxt[(n0 + 1) * ROWS + 2 * i + 1] = fmaxf(hi, 0.0f);
    }
}

__global__ void __launch_bounds__(NTHREADS, 4) lv_step_kernel(
    const float* __restrict__ W0, const float* __restrict__ b0,
    const float* __restrict__ W1, const float* __restrict__ b1,
    const float* __restrict__ W2, const float* __restrict__ b2,
    const float* __restrict__ W3, const float* __restrict__ b3,
    const float* __restrict__ obs_init, const float* __restrict__ feature_init,
    const float* __restrict__ tn_store, const float* __restrict__ x1_store,
    const float* __restrict__ x2_store, const float* __restrict__ path_seed,
    float* __restrict__ out, int s) {
    __shared__ __align__(16) float actA[HH * ROWS];
    __shared__ __align__(16) float actB[HH * ROWS];
    __shared__ float inp_sh[ROWS][8];
    __shared__ float w3_sh[HH * 5];
    __shared__ float b3_sh[5];

    const int tid = threadIdx.x;
    const int row0 = blockIdx.x * ROWS;

    // stage W3/b3 into shared
    for (int i = tid; i < HH * 5; i += NTHREADS) w3_sh[i] = W3[i];
    if (tid < 5) b3_sh[tid] = b3[tid];

    // stage state (2 dims per particle) — warp 0
    if (tid < ROWS * 2) {
        int r = tid >> 1, d = tid & 1;
        int p = row0 + r;
        inp_sh[r][d] = (s == 0) ? obs_init[p * 2 + d] : g_state[p * 2 + d];
    }
    // stage features — warp 2
    if (s == 0) {
        if (tid >= 64 && tid < 64 + ROWS * 6) {
            int q = tid - 64;
            int r = q / 6, k = q % 6;
            inp_sh[r][2 + k] = feature_init[(row0 + r) * 6 + k];
        }
    } else {
        if (tid == 64) {
            // replicate the reference's sequential fp32 time accumulation exactly
            float t = feature_init[0];
            for (int j = 0; j < s; j++) t += DTC;
            int i = s - 1;
            float f1 = tn_store[i], f2 = x1_store[i], f3 = x2_store[i];
#pragma unroll
            for (int r = 0; r < ROWS; r++) {
                inp_sh[r][2] = t;  inp_sh[r][3] = f1; inp_sh[r][4] = f2;
                inp_sh[r][5] = f3; inp_sh[r][6] = f2; inp_sh[r][7] = f3;
            }
        }
    }
    __syncthreads();

    // layer 0: (rows x 8) @ (8 x 256) + relu -> actA[n][r], 2 cols per thread
    {
        const int n0 = 2 * tid;
        float2 w0c[8];
#pragma unroll
        for (int k = 0; k < 8; k++)
            w0c[k] = *reinterpret_cast<const float2*>(W0 + k * HH + n0);
        float bb0 = b0[n0], bb1 = b0[n0 + 1];
#pragma unroll
        for (int r = 0; r < ROWS; r++) {
            float a0 = bb0, a1 = bb1;
#pragma unroll
            for (int k = 0; k < 8; k++) {
                float x = inp_sh[r][k];
                a0 = fmaf(x, w0c[k].x, a0);
                a1 = fmaf(x, w0c[k].y, a1);
            }
            actA[n0 * ROWS + r]       = fmaxf(a0, 0.0f);
            actA[(n0 + 1) * ROWS + r] = fmaxf(a1, 0.0f);
        }
    }
    __syncthreads();

    mlp_layer(actA, actB, W1, b1, tid);
    __syncthreads();
    mlp_layer(actB, actA, W2, b2, tid);
    __syncthreads();

    // layer 3: (rows x 256) @ (256 x 5), split-K over 16 lanes per row
    const int r = tid >> 4;
    const int l16 = tid & 15;
    float acc5[5] = {0.f, 0.f, 0.f, 0.f, 0.f};
#pragma unroll
    for (int kk = 0; kk < 16; kk++) {
        int k = l16 + (kk << 4);
        float a = actA[k * ROWS + r];
#pragma unroll
        for (int m = 0; m < 5; m++) acc5[m] = fmaf(a, w3_sh[k * 5 + m], acc5[m]);
    }
#pragma unroll
    for (int off = 8; off >= 1; off >>= 1) {
#pragma unroll
        for (int m = 0; m < 5; m++)
            acc5[m] += __shfl_down_sync(0xffffffffu, acc5[m], off, 16);
    }

    if (l16 == 0) {
        int p = row0 + r;
        float mu0 = acc5[0] + b3_sh[0];
        float mu1 = acc5[1] + b3_sh[1];
        float s11 = softplusf(acc5[2] + b3_sh[2]);
        float s21 = acc5[3] + b3_sh[3];
        float s22 = softplusf(acc5[4] + b3_sh[4]);
        float st0 = inp_sh[r][0], st1 = inp_sh[r][1];
        float e0 = path_seed[s * PP * 2 + p * 2 + 0];
        float e1 = path_seed[s * PP * 2 + p * 2 + 1];
        float n0 = softplusf(st0 + DTC * mu0 + SQRT_DTC * (s11 * e0));
        float n1 = softplusf(st1 + DTC * mu1 + SQRT_DTC * (s21 * e0 + s22 * e1));
        g_state[p * 2 + 0] = n0;
        g_state[p * 2 + 1] = n1;

        // path: out[p*202 + d*101 + t]; step s writes t = s+1
        out[p * 202 + (s + 1)]       = n0;
        out[p * 202 + 101 + (s + 1)] = n1;
        if (s == 0) {  // t = 0 comes from obs_init
            out[p * 202 + 0]   = st0;
            out[p * 202 + 101] = st1;
        }
        // mu_store: base P*202, [(p*100 + s)*2 + d]
        int mb = PP * 202 + (p * 100 + s) * 2;
        out[mb + 0] = mu0;
        out[mb + 1] = mu1;
        // sigma_store: base P*202 + P*200, [(p*100 + s)*4 + i*2 + j]
        int sb = PP * 202 + PP * 200 + (p * 100 + s) * 4;
        out[sb + 0] = s11;
        out[sb + 1] = 0.0f;   // chol[0][1]
        out[sb + 2] = s21;
        out[sb + 3] = s22;
    }
}

extern "C" void kernel_launch(void* const* d_in, const int* in_sizes, int n_in,
                              void* d_out, int out_size) {
    const float* W0 = (const float*)d_in[0];
    const float* b0 = (const float*)d_in[1];
    const float* W1 = (const float*)d_in[2];
    const float* b1 = (const float*)d_in[3];
    const float* W2 = (const float*)d_in[4];
    const float* b2 = (const float*)d_in[5];
    const float* W3 = (const float*)d_in[6];
    const float* b3 = (const float*)d_in[7];
    const float* obs_init = (const float*)d_in[8];
    const float* feature_init = (const float*)d_in[9];
    const float* tn_store = (const float*)d_in[10];
    const float* x1_store = (const float*)d_in[11];
    const float* x2_store = (const float*)d_in[12];
    const float* path_seed = (const float*)d_in[13];
    float* out = (float*)d_out;

    dim3 grid(NBLOCKS);   // 512 blocks
    dim3 block(NTHREADS);
    for (int s = 0; s < NSTEPS; s++) {
        lv_step_kernel<<<grid, block>>>(W0, b0, W1, b1, W2, b2, W3, b3,
                                        obs_init, feature_init, tn_store,
                                        x1_store, x2_store, path_seed, out, s);
    }
}